// round 14
// baseline (speedup 1.0000x reference)
#include <cuda_runtime.h>
#include <math.h>

#define BB 64
#define TT 2048
#define FF 64
#define KK 512
#define DD 512
#define LN_EPS 1e-5f
#define G_MIN 0.05f
#define G_MAX 0.95f
#define NSL 16         // split-K slices (phase 1)
#define NP2 32         // phase-2 blocks (16 d-rows each)
#define GRID 129
#define NT 512
#define CH 16          // timesteps per phase-3 chunk (n~12 -> single chunk)
#define ADSTR 132      // sAtDup row stride in floats

// Scratch (__device__ globals; zero-initialized at load).
// gMpart/gMt/gCp/gV are fully STG-overwritten each call (single buffer, no zero).
// gAB/gUB/gCsB are red targets -> double-buffered; idle blocks zero buf (e+1)&1.
__device__ __align__(16) float gMpart[NSL * DD * FF];  // [ks][fh][d][2] split-K partials
__device__ __align__(16) float gMt[FF * DD];           // [fh][d][2] reduced M
__device__ __align__(16) float gAB[2][FF * FF];        // raw A = M^T M (red.v2)
__device__ __align__(16) float gUB[2][FF];             // raw u = sum_d c'[d] M[d][f]
__device__ __align__(16) float gCsB[2][FF];            // raw colsum_d M[d][f]
__device__ __align__(16) float gCp[DD];                // c' = (W_b+b) - mean
__device__ float gV[1];                                // raw ||c'||^2
__device__ unsigned int gC0, gC1;                      // monotonic barrier counters
__device__ unsigned int gEpoch;                        // +1 per call (stable at entry)

__device__ __forceinline__ unsigned long long pack2(float lo, float hi) {
    unsigned long long r;
    asm("mov.b64 %0, {%1, %2};" : "=l"(r) : "f"(lo), "f"(hi));
    return r;
}
__device__ __forceinline__ void unpack2(unsigned long long p, float& lo, float& hi) {
    asm("mov.b64 {%0, %1}, %2;" : "=f"(lo), "=f"(hi) : "l"(p));
}
__device__ __forceinline__ void fma2(unsigned long long& d, unsigned long long a, unsigned long long b) {
    asm("fma.rn.f32x2 %0, %1, %2, %0;" : "+l"(d) : "l"(a), "l"(b));
}
__device__ __forceinline__ void redadd2(float* p, float v0, float v1) {
    asm volatile("red.global.v2.f32.add [%0], {%1, %2};" :: "l"(p), "f"(v0), "f"(v1) : "memory");
}
__device__ __forceinline__ void redadd1(float* p, float v) {
    asm volatile("red.global.add.f32 [%0], %1;" :: "l"(p), "f"(v) : "memory");
}
__device__ __forceinline__ void cpasync16(float* smem_dst, const float* gsrc) {
    unsigned int sa = (unsigned int)__cvta_generic_to_shared(smem_dst);
    asm volatile("cp.async.ca.shared.global [%0], [%1], 16;" :: "r"(sa), "l"(gsrc));
}
__device__ __forceinline__ void rel_inc(unsigned int* c) {
    asm volatile("red.release.gpu.global.add.u32 [%0], %1;" :: "l"(c), "r"(1u) : "memory");
}
__device__ __forceinline__ void spin_ge(volatile unsigned int* c, unsigned int target) {
    while (*c < target) { }
    __threadfence();
}

__global__ void __launch_bounds__(NT, 1)
mega(const float* __restrict__ x,
     const float* __restrict__ th1, const float* __restrict__ ph1,
     const float* __restrict__ th2, const float* __restrict__ ph2,
     const float* __restrict__ w1p, const float* __restrict__ w2p,
     const float* __restrict__ bgp,
     const float* __restrict__ Pw,  const float* __restrict__ Ww,
     const float* __restrict__ Wb,  const float* __restrict__ bvec,
     const float* __restrict__ gamma, const float* __restrict__ beta,
     float* __restrict__ out) {
    __shared__ __align__(16) float sBig[8192];       // P1 tiles / P2 sS / P3 sA
    __shared__ __align__(16) float sXst[CH * 64];    // staged x chunk
    __shared__ __align__(16) float sXt[64];
    __shared__ float sU[64], sCs[64], sCf[CH], sCpS[16];
    __shared__ unsigned int sEpoch;

    const int tid = threadIdx.x;
    const int bid = blockIdx.x;
    const int wid = tid >> 5, lane = tid & 31;

    if (tid == 0) sEpoch = *(volatile unsigned int*)&gEpoch;   // stable: launches serialized

    // ---------------- prologue: async chunk-0 x staging (blocks 0..63) ----------------
    const float* xb = x + (size_t)bid * TT * FF;
    if (bid < 64) {
        const int q = tid >> 4, f4 = tid & 15;
        if (q < CH)
            cpasync16(sXst + q * 64 + f4 * 4, xb + (size_t)(TT - 1 - q) * FF + f4 * 4);
        asm volatile("cp.async.commit_group;" ::: "memory");
    }

    // ---------------- Phase 1: 128 GEMM blocks (STG partials) + block 128 (c', v) ----------------
    if (bid < 128) {
        float* sAtDup = sBig;                 // [k][d] dup pairs, stride ADSTR
        float* sB     = sBig + 32 * ADSTR;    // [k][f] 32x64
        const int ct = bid & 7;               // d tile
        const int ks = bid >> 3;              // k slice (16)
        const int d0 = ct * 64, k0 = ks * 32;

        {
            const int kq = tid & 7, dy = tid >> 3;
            float4 w4 = *reinterpret_cast<const float4*>(Ww + (size_t)(d0 + dy) * KK + k0 + kq * 4);
            *reinterpret_cast<float2*>(sAtDup + (kq * 4 + 0) * ADSTR + dy * 2) = make_float2(w4.x, w4.x);
            *reinterpret_cast<float2*>(sAtDup + (kq * 4 + 1) * ADSTR + dy * 2) = make_float2(w4.y, w4.y);
            *reinterpret_cast<float2*>(sAtDup + (kq * 4 + 2) * ADSTR + dy * 2) = make_float2(w4.z, w4.z);
            *reinterpret_cast<float2*>(sAtDup + (kq * 4 + 3) * ADSTR + dy * 2) = make_float2(w4.w, w4.w);
            const int fq = tid & 15, ky = tid >> 4;
            float4 p4 = *reinterpret_cast<const float4*>(Pw + (size_t)(k0 + ky) * FF + fq * 4);
            *reinterpret_cast<float4*>(sB + ky * 64 + fq * 4) = p4;
        }
        __syncthreads();

        const int tx = ((wid & 1) << 3) + (lane & 7);    // 0..15 (4 f each)
        const int ty = ((wid >> 1) << 2) + (lane >> 3);  // 0..31 (2 d each)

        unsigned long long acc2[2][2];
        acc2[0][0] = acc2[0][1] = acc2[1][0] = acc2[1][1] = pack2(0.f, 0.f);
#pragma unroll 8
        for (int k = 0; k < 32; k++) {
            ulonglong2 aD = *reinterpret_cast<const ulonglong2*>(sAtDup + k * ADSTR + ty * 4);
            ulonglong2 bD = *reinterpret_cast<const ulonglong2*>(sB + k * 64 + tx * 4);
            fma2(acc2[0][0], aD.x, bD.x);
            fma2(acc2[0][1], aD.x, bD.y);
            fma2(acc2[1][0], aD.y, bD.x);
            fma2(acc2[1][1], aD.y, bD.y);
        }
        // STG partial pairs: gMpart[ks][fh][d][2]
        const int d = d0 + ty * 2;
#pragma unroll
        for (int i = 0; i < 2; i++)
#pragma unroll
            for (int jp = 0; jp < 2; jp++) {
                const int fh = tx * 2 + jp;
                *reinterpret_cast<unsigned long long*>(
                    gMpart + (size_t)ks * 32768 + (size_t)fh * 1024 + (size_t)(d + i) * 2) = acc2[i][jp];
            }
        __syncthreads();                       // sBig free; publishes STGs before release
    } else {
        // block 128: c' = (W_b + b) - mean ; vraw = ||c'||^2
        const float cv = Wb[tid] + bvec[tid];
        float s1 = cv;
#pragma unroll
        for (int o = 16; o > 0; o >>= 1) s1 += __shfl_down_sync(0xffffffffu, s1, o);
        if (lane == 0) sBig[wid] = s1;
        __syncthreads();
        if (wid == 0) {
            float t0 = (lane < 16) ? sBig[lane] : 0.f;
#pragma unroll
            for (int o = 8; o > 0; o >>= 1) t0 += __shfl_down_sync(0xffffffffu, t0, o);
            if (lane == 0) sBig[16] = t0;
        }
        __syncthreads();
        const float cbar = sBig[16] * (1.0f / DD);
        const float cp = cv - cbar;
        gCp[tid] = cp;
        __syncthreads();
        float v1 = cp * cp;
#pragma unroll
        for (int o = 16; o > 0; o >>= 1) v1 += __shfl_down_sync(0xffffffffu, v1, o);
        if (lane == 0) sBig[wid] = v1;
        __syncthreads();
        if (wid == 0) {
            float t0 = (lane < 16) ? sBig[lane] : 0.f;
#pragma unroll
            for (int o = 8; o > 0; o >>= 1) t0 += __shfl_down_sync(0xffffffffu, t0, o);
            if (lane == 0) gV[0] = t0;
        }
        __syncthreads();
    }

    const unsigned int e = sEpoch;
    if (tid == 0) rel_inc(&gC0);

    // ---------------- role split ----------------
    if (bid >= 64 && bid < 64 + NP2) {
        // ====== Phase 2: reduce Mpart slice (16 d-rows), write gMt, tiny A/cs/u reds ======
        const int s = bid - 64;                // d-range [s*16, s*16+16)
        float* sS = sBig;                      // [d_local][f] stride 68
        if (tid == 0) spin_ge(&gC0, (e + 1u) * GRID);
        __syncthreads();

        if (tid < 16) sCpS[tid] = gCp[s * 16 + tid];
        if (tid < 256) {
            const int fh = tid >> 3, dq = tid & 7;          // 32 fh x 8 d-quads
            const size_t off = (size_t)fh * 1024 + (size_t)s * 32 + (size_t)dq * 4;
            float4 a = make_float4(0.f, 0.f, 0.f, 0.f);
#pragma unroll
            for (int ks = 0; ks < NSL; ks++) {
                float4 v = *reinterpret_cast<const float4*>(gMpart + (size_t)ks * 32768 + off);
                a.x += v.x; a.y += v.y; a.z += v.z; a.w += v.w;
            }
            *reinterpret_cast<float4*>(gMt + off) = a;
            const int dl = dq * 2;
            sS[(dl + 0) * 68 + fh * 2 + 0] = a.x;   // f=2fh   @ d
            sS[(dl + 0) * 68 + fh * 2 + 1] = a.y;   // f=2fh+1 @ d
            sS[(dl + 1) * 68 + fh * 2 + 0] = a.z;   // f=2fh   @ d+1
            sS[(dl + 1) * 68 + fh * 2 + 1] = a.w;   // f=2fh+1 @ d+1
        }
        __syncthreads();

        // A-partial = sS^T sS over 16 rows
        {
            const int tx = tid & 15, ty = tid >> 4;         // f2 quad, f1 pair
            float acc[2][4];
#pragma unroll
            for (int i = 0; i < 2; i++)
#pragma unroll
                for (int j = 0; j < 4; j++) acc[i][j] = 0.f;
#pragma unroll
            for (int d = 0; d < 16; d++) {
                float a0 = sS[d * 68 + ty * 2 + 0];
                float a1 = sS[d * 68 + ty * 2 + 1];
                float4 b4 = *reinterpret_cast<const float4*>(sS + d * 68 + tx * 4);
                acc[0][0] += a0 * b4.x; acc[0][1] += a0 * b4.y; acc[0][2] += a0 * b4.z; acc[0][3] += a0 * b4.w;
                acc[1][0] += a1 * b4.x; acc[1][1] += a1 * b4.y; acc[1][2] += a1 * b4.z; acc[1][3] += a1 * b4.w;
            }
            float* ab = gAB[e & 1];
#pragma unroll
            for (int i = 0; i < 2; i++) {
                const int f1 = ty * 2 + i;
                redadd2(&ab[(size_t)f1 * FF + tx * 4 + 0], acc[i][0], acc[i][1]);
                redadd2(&ab[(size_t)f1 * FF + tx * 4 + 2], acc[i][2], acc[i][3]);
            }
        }
        // colsum / u partials (threads 0..63)
        if (tid < 64) {
            float cs = 0.f, up = 0.f;
#pragma unroll
            for (int d = 0; d < 16; d++) {
                float m = sS[d * 68 + tid];
                cs += m;
                up += sCpS[d] * m;
            }
            redadd1(&gCsB[e & 1][tid], cs);
            redadd1(&gUB[e & 1][tid], up);
        }
        __syncthreads();
        if (tid == 0) rel_inc(&gC1);
    } else if (bid >= 64 + NP2 && bid < 128) {
        // ====== zero next-epoch red targets (off critical path) ======
        const int zb = bid - (64 + NP2);       // 0..31
        const int idx = zb * NT + tid;         // covers 16384 >= 4096
        if (idx < FF * FF) gAB[(e + 1u) & 1][idx] = 0.f;
        if (zb == 0 && tid < 64) {
            gUB[(e + 1u) & 1][tid] = 0.f;
            gCsB[(e + 1u) & 1][tid] = 0.f;
        }
    } else if (bid == 128) {
        if (tid == 0) atomicAdd(&gEpoch, 1u);  // read only at next-call entry (post-drain)
    }

    if (bid >= 64) return;

    // ---------------- Phase 3: blocks 0..63, one per batch ----------------
    {
        float* sA = sBig;                      // RAW A, stride 65
        if (tid == 0) spin_ge(&gC1, (e + 1u) * NP2);

        // gate math overlaps the spin
        const float z1 = cosf(th1[0]) * cosf(ph1[0]);
        const float z2 = cosf(th2[0]) * cosf(ph2[0]);
        const float zg = w1p[0] * z1 + w2p[0] * z2 + bgp[0];
        float g = 1.0f / (1.0f + expf(-zg));
        g = fminf(fmaxf(g, G_MIN), G_MAX);
        const float omg = 1.0f - g;
        const float l2omg = log2f(omg);
        int n = (int)ceilf(-23.03f / logf(omg));
        if (n < 1) n = 1;
        if (n > TT) n = TT;
        __syncthreads();

        // M row (d = tid) as f32x2 pairs, coalesced u64 loads
        unsigned long long m2[32];
#pragma unroll
        for (int q = 0; q < 32; q++)
            m2[q] = *reinterpret_cast<const unsigned long long*>(gMt + (size_t)q * 1024 + tid * 2);

        // raw A -> smem (stride 65)
        const float4* ga4 = reinterpret_cast<const float4*>(gAB[e & 1]);
#pragma unroll
        for (int r = 0; r < 2; r++) {
            const int idx = r * NT + tid;      // 0..1023
            const int f1 = idx >> 4, fq = idx & 15;
            float4 v = ga4[idx];
            sA[f1 * 65 + fq * 4 + 0] = v.x;
            sA[f1 * 65 + fq * 4 + 1] = v.y;
            sA[f1 * 65 + fq * 4 + 2] = v.z;
            sA[f1 * 65 + fq * 4 + 3] = v.w;
        }
        if (tid < 64) {
            sU[tid] = gUB[e & 1][tid];
            sCs[tid] = gCsB[e & 1][tid];
        }
        const float vraw = gV[0];
        const float cp = gCp[tid];
        asm volatile("cp.async.wait_group 0;" ::: "memory");
        __syncthreads();

        float xacc = 0.f;                      // threads 0..63: Xtilde[tid]
        float Sacc = 0.f;                      // redundant across threads

        for (int jc = 0; jc < n; jc += CH) {
            const int cnt = min(CH, n - jc);
            if (jc != 0) {
                __syncthreads();
                const int q = tid >> 4, f4 = tid & 15;
                if (q < cnt) {
                    const float4* xr = reinterpret_cast<const float4*>(xb + (size_t)(TT - 1 - (jc + q)) * FF);
                    *reinterpret_cast<float4*>(sXst + q * 64 + f4 * 4) = xr[f4];
                }
                __syncthreads();
            }

            // warp wid handles timestep jc+wid: quadratic-form variance
            {
                const float* xt = sXst + wid * 64;
                const float x_a = xt[lane], x_b = xt[lane + 32];
                float accA = 0.f, accB = 0.f;
#pragma unroll 8
                for (int f2 = 0; f2 < 64; f2++) {
                    const float xv = xt[f2];
                    accA += sA[lane * 65 + f2] * xv;
                    accB += sA[(lane + 32) * 65 + f2] * xv;
                }
                float p = x_a * (accA + 2.0f * sU[lane]) + x_b * (accB + 2.0f * sU[lane + 32]);
                float q = sCs[lane] * x_a + sCs[lane + 32] * x_b;
#pragma unroll
                for (int o = 16; o > 0; o >>= 1) {
                    p += __shfl_down_sync(0xffffffffu, p, o);
                    q += __shfl_down_sync(0xffffffffu, q, o);
                }
                if (lane == 0) {
                    const float mu = q * (1.0f / DD);
                    const float var = (p + vraw) * (1.0f / DD) - mu * mu;
                    const float wt = g * exp2f((float)(jc + wid) * l2omg);
                    sCf[wid] = (wid < cnt) ? (wt * rsqrtf(var + LN_EPS)) : 0.f;
                }
            }
            __syncthreads();

            if (tid < 64) {
#pragma unroll
                for (int t = 0; t < CH; t++) xacc += sCf[t] * sXst[t * 64 + tid];
            }
#pragma unroll
            for (int t = 0; t < CH; t++) Sacc += sCf[t];
        }

        __syncthreads();
        if (tid < 64) sXt[tid] = xacc;
        __syncthreads();

        // mdot = (colsum . Xt)/D, redundant per thread (broadcast LDS)
        float mdot = 0.f;
#pragma unroll 8
        for (int f = 0; f < 64; f++) mdot += sCs[f] * sXt[f];
        mdot *= (1.0f / DD);

        // GEMV: dot = M[d] . Xt via 32 fma2
        unsigned long long accd = pack2(0.f, 0.f);
        const unsigned long long* xt2 = reinterpret_cast<const unsigned long long*>(sXt);
#pragma unroll
        for (int q = 0; q < 32; q++) fma2(accd, m2[q], xt2[q]);
        float dl, dh;
        unpack2(accd, dl, dh);
        const float dot = dl + dh;

        const float Wsum = 1.0f - exp2f((float)TT * l2omg);
        out[(size_t)bid * DD + tid] = gamma[tid] * (dot - mdot + cp * Sacc) + beta[tid] * Wsum;
    }
}

// ---------------------------------------------------------------------------
// Inputs: x, theta1, phi1, theta2, phi2, w1, w2, b_g, P_w, W_w, W_b, b,
//         ln_gamma, ln_beta, alpha (alpha cancels inside LayerNorm).
// ---------------------------------------------------------------------------
extern "C" void kernel_launch(void* const* d_in, const int* in_sizes, int n_in,
                              void* d_out, int out_size) {
    const float* x     = (const float*)d_in[0];
    const float* th1   = (const float*)d_in[1];
    const float* ph1   = (const float*)d_in[2];
    const float* th2   = (const float*)d_in[3];
    const float* ph2   = (const float*)d_in[4];
    const float* w1p   = (const float*)d_in[5];
    const float* w2p   = (const float*)d_in[6];
    const float* bgp   = (const float*)d_in[7];
    const float* Pw    = (const float*)d_in[8];
    const float* Ww    = (const float*)d_in[9];
    const float* Wb    = (const float*)d_in[10];
    const float* bvec  = (const float*)d_in[11];
    const float* gamma = (const float*)d_in[12];
    const float* beta  = (const float*)d_in[13];

    mega<<<GRID, NT>>>(x, th1, ph1, th2, ph2, w1p, w2p, bgp,
                       Pw, Ww, Wb, bvec, gamma, beta, (float*)d_out);
}

// round 15
// speedup vs baseline: 1.2916x; 1.2916x over previous
#include <cuda_runtime.h>
#include <math.h>

#define BB 64
#define TT 2048
#define FF 64
#define KK 512
#define DD 512
#define LN_EPS 1e-5f
#define G_MIN 0.05f
#define G_MAX 0.95f
#define GRID 129
#define NT 512
#define CH 8           // LOCAL timesteps per phase-3 chunk (n~12 -> 6 per parity)
#define ADSTR 132      // sAtDup row stride in floats

// Scratch (__device__ globals; zero-initialized at load).
// Double-buffered interleaved M: buf[e&1], layout [f/2][d][2]; every block zeroes
// a 256-float slice of buf (e+1)&1 during call e (during its spin window).
__device__ __align__(16) float gMtBuf[2][FF * DD];
__device__ __align__(16) float gCp[DD];                 // c' = (W_b+b) - mean
__device__ __align__(16) float gHpart[BB * DD];         // odd-parity partial hacc
__device__ unsigned int gC0;                            // +GRID per call (monotonic)
__device__ unsigned int gPairC[BB];                     // +1 per call each (monotonic)

__device__ __forceinline__ unsigned long long pack2(float lo, float hi) {
    unsigned long long r;
    asm("mov.b64 %0, {%1, %2};" : "=l"(r) : "f"(lo), "f"(hi));
    return r;
}
__device__ __forceinline__ void unpack2(unsigned long long p, float& lo, float& hi) {
    asm("mov.b64 {%0, %1}, %2;" : "=f"(lo), "=f"(hi) : "l"(p));
}
// Packed dual-fp32 FMA (Blackwell f32x2 pipe)
__device__ __forceinline__ void fma2(unsigned long long& d, unsigned long long a, unsigned long long b) {
    asm("fma.rn.f32x2 %0, %1, %2, %0;" : "+l"(d) : "l"(a), "l"(b));
}
__device__ __forceinline__ void redadd2(float* p, float v0, float v1) {
    asm volatile("red.global.v2.f32.add [%0], {%1, %2};" :: "l"(p), "f"(v0), "f"(v1) : "memory");
}
__device__ __forceinline__ void cpasync16(float* smem_dst, const float* gsrc) {
    unsigned int sa = (unsigned int)__cvta_generic_to_shared(smem_dst);
    asm volatile("cp.async.ca.shared.global [%0], [%1], 16;" :: "r"(sa), "l"(gsrc));
}
__device__ __forceinline__ void rel_inc(unsigned int* c) {
    asm volatile("red.release.gpu.global.add.u32 [%0], %1;" :: "l"(c), "r"(1u) : "memory");
}
__device__ __forceinline__ void spin_ge(volatile unsigned int* c, unsigned int target) {
    while (*c < target) { }
    __threadfence();
}

__global__ void __launch_bounds__(NT, 1)
mega(const float* __restrict__ x,
     const float* __restrict__ th1, const float* __restrict__ ph1,
     const float* __restrict__ th2, const float* __restrict__ ph2,
     const float* __restrict__ w1p, const float* __restrict__ w2p,
     const float* __restrict__ bgp,
     const float* __restrict__ Pw,  const float* __restrict__ Ww,
     const float* __restrict__ Wb,  const float* __restrict__ bvec,
     const float* __restrict__ gamma, const float* __restrict__ beta,
     float* __restrict__ out) {
    __shared__ __align__(16) float sBig[6272];       // P1 tiles (6272) / sY (CH*NT=4096)
    __shared__ __align__(16) float sXst[CH * 64];    // staged x chunk
    __shared__ float sMu[CH], sCf[CH];
    __shared__ unsigned int sEpoch;

    const int tid = threadIdx.x;
    const int bid = blockIdx.x;
    const int wid = tid >> 5, lane = tid & 31;

    // epoch: stable pre-increment value (all prior launches fully drained)
    if (tid == 0) sEpoch = (*(volatile unsigned int*)&gC0) / GRID;

    // ---------------- prologue: async x staging for this block's parity ----------------
    const int pb = bid & 63;                  // batch
    const int par = (bid >> 6) & 1;           // parity: 0 = even j, 1 = odd j
    const float* xb = x + (size_t)pb * TT * FF;
    if (bid < 128) {
        const int q = tid >> 4, f4 = tid & 15;
        if (q < CH) {
            const int j = 2 * q + par;        // global timestep offset from the end
            cpasync16(sXst + q * 64 + f4 * 4, xb + (size_t)(TT - 1 - j) * FF + f4 * 4);
        }
        asm volatile("cp.async.commit_group;" ::: "memory");
    }

    // ---------------- Phase 1: 128 GEMM blocks (f32x2, red.v2) + block 128 (c') ----------------
    if (bid < 128) {
        float* sAtDup = sBig;                 // [k][d] dup pairs, stride ADSTR
        float* sB     = sBig + 32 * ADSTR;    // [k][f] 32x64
        const int ct = bid & 7;               // d tile
        const int ks = bid >> 3;              // k slice (16)
        const int d0 = ct * 64, k0 = ks * 32;

        {
            const int kq = tid & 7, dy = tid >> 3;
            float4 w4 = *reinterpret_cast<const float4*>(Ww + (size_t)(d0 + dy) * KK + k0 + kq * 4);
            *reinterpret_cast<float2*>(sAtDup + (kq * 4 + 0) * ADSTR + dy * 2) = make_float2(w4.x, w4.x);
            *reinterpret_cast<float2*>(sAtDup + (kq * 4 + 1) * ADSTR + dy * 2) = make_float2(w4.y, w4.y);
            *reinterpret_cast<float2*>(sAtDup + (kq * 4 + 2) * ADSTR + dy * 2) = make_float2(w4.z, w4.z);
            *reinterpret_cast<float2*>(sAtDup + (kq * 4 + 3) * ADSTR + dy * 2) = make_float2(w4.w, w4.w);
            const int fq = tid & 15, ky = tid >> 4;
            float4 p4 = *reinterpret_cast<const float4*>(Pw + (size_t)(k0 + ky) * FF + fq * 4);
            *reinterpret_cast<float4*>(sB + ky * 64 + fq * 4) = p4;
        }
        __syncthreads();

        const int tx = ((wid & 1) << 3) + (lane & 7);    // 0..15 (4 f each)
        const int ty = ((wid >> 1) << 2) + (lane >> 3);  // 0..31 (2 d each)

        unsigned long long acc2[2][2];
        acc2[0][0] = acc2[0][1] = acc2[1][0] = acc2[1][1] = pack2(0.f, 0.f);
#pragma unroll 8
        for (int k = 0; k < 32; k++) {
            ulonglong2 aD = *reinterpret_cast<const ulonglong2*>(sAtDup + k * ADSTR + ty * 4);
            ulonglong2 bD = *reinterpret_cast<const ulonglong2*>(sB + k * 64 + tx * 4);
            fma2(acc2[0][0], aD.x, bD.x);
            fma2(acc2[0][1], aD.x, bD.y);
            fma2(acc2[1][0], aD.y, bD.x);
            fma2(acc2[1][1], aD.y, bD.y);
        }
        float* mbuf = gMtBuf[sEpoch & 1];
        const int d = d0 + ty * 2;
#pragma unroll
        for (int i = 0; i < 2; i++)
#pragma unroll
            for (int jp = 0; jp < 2; jp++) {
                float f0, f1;
                unpack2(acc2[i][jp], f0, f1);
                const int fh = tx * 2 + jp;            // f-pair index
                redadd2(&mbuf[(size_t)fh * 1024 + (d + i) * 2], f0, f1);
            }
        __syncthreads();                       // sBig free for sY reuse
    } else {
        // block 128: c' = (W_b + b) - mean
        const float cv = Wb[tid] + bvec[tid];
        float s1 = cv;
#pragma unroll
        for (int o = 16; o > 0; o >>= 1) s1 += __shfl_down_sync(0xffffffffu, s1, o);
        if (lane == 0) sBig[wid] = s1;
        __syncthreads();
        if (wid == 0) {
            float t0 = (lane < 16) ? sBig[lane] : 0.f;
#pragma unroll
            for (int o = 8; o > 0; o >>= 1) t0 += __shfl_down_sync(0xffffffffu, t0, o);
            if (lane == 0) sBig[16] = t0;
        }
        __syncthreads();
        const float cbar = sBig[16] * (1.0f / DD);
        gCp[tid] = cv - cbar;
    }

    const unsigned int e = sEpoch;
    // producer-done (release)
    if (tid == 0) rel_inc(&gC0);

    if (bid >= 128) return;

    // zero next-epoch buffer slice (hides in the spin window; disjoint from buf e&1)
    if (tid < 256) gMtBuf[(e + 1u) & 1][(size_t)bid * 256 + tid] = 0.f;

    // gate math (overlaps thread-0 spin)
    if (tid == 0) spin_ge(&gC0, (e + 1u) * GRID);
    const float z1 = cosf(th1[0]) * cosf(ph1[0]);
    const float z2 = cosf(th2[0]) * cosf(ph2[0]);
    const float zg = w1p[0] * z1 + w2p[0] * z2 + bgp[0];
    float g = 1.0f / (1.0f + expf(-zg));
    g = fminf(fmaxf(g, G_MIN), G_MAX);
    const float omg = 1.0f - g;
    const float l2omg = log2f(omg);
    int n = (int)ceilf(-23.03f / logf(omg));
    if (n < 1) n = 1;
    if (n > TT) n = TT;
    const int nloc = (n + 1 - par) >> 1;       // this block's timestep count
    __syncthreads();

    // ---------------- Phase 3: pair (pb, pb+64) splits timesteps by parity ----------------
    {
        const float* mbuf = gMtBuf[e & 1];
        float* sY = sBig;
        // m2[q] = (M[2q][d], M[2q+1][d]) : coalesced u64 loads
        unsigned long long m2[32];
#pragma unroll
        for (int q = 0; q < 32; q++)
            m2[q] = *reinterpret_cast<const unsigned long long*>(mbuf + (size_t)q * 1024 + tid * 2);
        const float cp = gCp[tid];
        asm volatile("cp.async.wait_group 0;" ::: "memory");
        __syncthreads();
        float hacc = 0.f;

        for (int lc = 0; lc < nloc; lc += CH) {
            const int cnt = min(CH, nloc - lc);
            if (lc != 0) {
                __syncthreads();
                const int q = tid >> 4, f4 = tid & 15;
                if (q < cnt) {
                    const int j = 2 * (lc + q) + par;
                    const float4* xr = reinterpret_cast<const float4*>(xb + (size_t)(TT - 1 - j) * FF);
                    *reinterpret_cast<float4*>(sXst + q * 64 + f4 * 4) = xr[f4];
                }
                __syncthreads();
            }

            // y for cnt local timesteps: pure FFMA2 stream
#pragma unroll
            for (int tq = 0; tq < CH; tq++) {
                if (tq < cnt) {
                    unsigned long long acc2a = pack2(cp, 0.f);
                    unsigned long long acc2b = pack2(0.f, 0.f);
                    const ulonglong2* xs = reinterpret_cast<const ulonglong2*>(sXst + tq * 64);
#pragma unroll
                    for (int q = 0; q < 16; q++) {
                        ulonglong2 xv = xs[q];
                        fma2(acc2a, m2[2 * q + 0], xv.x);
                        fma2(acc2b, m2[2 * q + 1], xv.y);
                    }
                    float lo, hi, lo2, hi2;
                    unpack2(acc2a, lo, hi);
                    unpack2(acc2b, lo2, hi2);
                    sY[tq * NT + tid] = (lo + lo2) + (hi + hi2);
                }
            }
            __syncthreads();

            // warp wid reduces local timestep wid: (sum y, sum y^2)
            if (wid < cnt) {
                const float* yr = sY + wid * NT;
                float s1 = 0.f, s2 = 0.f;
#pragma unroll
                for (int i = 0; i < 16; i++) {
                    float vv = yr[lane + 32 * i];
                    s1 += vv;
                    s2 += vv * vv;
                }
#pragma unroll
                for (int o = 16; o > 0; o >>= 1) {
                    s1 += __shfl_down_sync(0xffffffffu, s1, o);
                    s2 += __shfl_down_sync(0xffffffffu, s2, o);
                }
                if (lane == 0) {
                    const float mu = s1 * (1.0f / DD);
                    const float var = s2 * (1.0f / DD) - mu * mu;
                    const int j = 2 * (lc + wid) + par;
                    sMu[wid] = mu;
                    sCf[wid] = g * exp2f((float)j * l2omg) * rsqrtf(var + LN_EPS);
                }
            }
            __syncthreads();

#pragma unroll
            for (int t = 0; t < CH; t++) {
                if (t < cnt)
                    hacc += sCf[t] * (sY[t * NT + tid] - sMu[t]);
            }
        }

        if (par == 1) {
            // odd half: publish partial, signal pair
            gHpart[(size_t)pb * DD + tid] = hacc;
            __syncthreads();
            if (tid == 0) rel_inc(&gPairC[pb]);
        } else {
            // even half: wait for partner, combine, output
            if (tid == 0) spin_ge(&gPairC[pb], e + 1u);
            __syncthreads();
            const float Wsum = 1.0f - exp2f((float)TT * l2omg);
            const float res = hacc + gHpart[(size_t)pb * DD + tid];
            out[(size_t)pb * DD + tid] = gamma[tid] * res + beta[tid] * Wsum;
        }
    }
}

// ---------------------------------------------------------------------------
// Inputs: x, theta1, phi1, theta2, phi2, w1, w2, b_g, P_w, W_w, W_b, b,
//         ln_gamma, ln_beta, alpha (alpha cancels inside LayerNorm).
// ---------------------------------------------------------------------------
extern "C" void kernel_launch(void* const* d_in, const int* in_sizes, int n_in,
                              void* d_out, int out_size) {
    const float* x     = (const float*)d_in[0];
    const float* th1   = (const float*)d_in[1];
    const float* ph1   = (const float*)d_in[2];
    const float* th2   = (const float*)d_in[3];
    const float* ph2   = (const float*)d_in[4];
    const float* w1p   = (const float*)d_in[5];
    const float* w2p   = (const float*)d_in[6];
    const float* bgp   = (const float*)d_in[7];
    const float* Pw    = (const float*)d_in[8];
    const float* Ww    = (const float*)d_in[9];
    const float* Wb    = (const float*)d_in[10];
    const float* bvec  = (const float*)d_in[11];
    const float* gamma = (const float*)d_in[12];
    const float* beta  = (const float*)d_in[13];

    mega<<<GRID, NT>>>(x, th1, ph1, th2, ph2, w1p, w2p, bgp,
                       Pw, Ww, Wb, bvec, gamma, beta, (float*)d_out);
}